// round 3
// baseline (speedup 1.0000x reference)
#include <cuda_runtime.h>
#include <cstdint>

#define NB   8192
#define NS   100
#define NE   64
#define NH1  128
#define NH2  64
#define NF   128   // k' = [k, k*q] dimension

// -------- device scratch (alloc-free) --------
__device__ float4 g_Wcat4[(NF * NH1) / 4];  // [f][h]: rows 0..63 = W0b - W0d, rows 64..127 = W0c
__device__ float  g_Wq[NE * NH1];           // [e][h]: W0a + W0d

// -------- f32x2 packed-FMA helpers --------
__device__ __forceinline__ unsigned long long pack2(float lo, float hi) {
    unsigned long long r;
    asm("mov.b64 %0, {%1, %2};" : "=l"(r) : "f"(lo), "f"(hi));
    return r;
}
__device__ __forceinline__ unsigned long long dup2(float v) {
    unsigned long long r;
    asm("mov.b64 %0, {%1, %1};" : "=l"(r) : "f"(v));
    return r;
}
__device__ __forceinline__ void fma2(unsigned long long& d, unsigned long long a,
                                     unsigned long long b) {
    asm("fma.rn.f32x2 %0, %1, %2, %0;" : "+l"(d) : "l"(a), "l"(b));
}
__device__ __forceinline__ float2 unpack2(unsigned long long v) {
    float lo, hi;
    asm("mov.b64 {%0, %1}, %2;" : "=f"(lo), "=f"(hi) : "l"(v));
    return make_float2(lo, hi);
}

// -------- prelude: fold W0 into Wcat / Wq --------
__global__ void prep_kernel(const float* __restrict__ W0) {
    int idx = blockIdx.x * blockDim.x + threadIdx.x;
    if (idx >= NF * NH1) return;
    int e = idx >> 7, h = idx & 127;
    float v;
    if (e < 64) v = W0[(64 + e) * NH1 + h] - W0[(192 + e) * NH1 + h];
    else        v = W0[(128 + (e - 64)) * NH1 + h];
    ((float*)g_Wcat4)[idx] = v;
    if (e < 64) g_Wq[idx] = W0[e * NH1 + h] + W0[(192 + e) * NH1 + h];
}

// -------- fused per-batch kernel: 1 CTA = 1 batch, 512 threads --------
// smem (floats): sWcat 16384 | sW1 8192 | sKp 12800 | sH0 12800 |
//                sC 128 | sQ 64 | sW2 64 | sB1 64 | sScore 104 | sPart 800
//                = 51400 floats = 205600 B
__global__ __launch_bounds__(512, 1)
void din_kernel(const float* __restrict__ q_g,
                const float* __restrict__ keys_g,
                const int*   __restrict__ klen_g,
                const float* __restrict__ b0_g,
                const float* __restrict__ W1_g,
                const float* __restrict__ b1_g,
                const float* __restrict__ W2_g,
                const float* __restrict__ b2_g,
                float* __restrict__ out_g,
                float* __restrict__ attn_g) {
    extern __shared__ float sm[];
    float* sWcat  = sm;                 // 16384
    float* sW1    = sWcat + 16384;      // 8192
    float* sKp    = sW1 + 8192;         // 12800  [s][f]  (f<64 = keys row)
    float* sH0    = sKp + 12800;        // 12800  [s][h]
    float* sC     = sH0 + 12800;        // 128
    float* sQ     = sC + 128;           // 64
    float* sW2    = sQ + 64;            // 64
    float* sB1    = sW2 + 64;           // 64
    float* sScore = sB1 + 64;           // 104
    float* sPart  = sScore + 104;       // 800

    const int b = blockIdx.x;
    const int t = threadIdx.x;
    const int len = klen_g[b];
    const float b2v = b2_g[0];

    // ---- load shared weights + q (vectorized) ----
    {
        float4* dw = (float4*)sWcat;
        for (int i = t; i < (NF * NH1) / 4; i += 512) dw[i] = g_Wcat4[i];
        const float4* gw1 = (const float4*)W1_g;
        float4* dw1 = (float4*)sW1;
        for (int i = t; i < (NH1 * NH2) / 4; i += 512) dw1[i] = gw1[i];
        if (t < 64) { sQ[t] = q_g[b * NE + t]; sW2[t] = W2_g[t]; sB1[t] = b1_g[t]; }
    }
    __syncthreads();

    // ---- c[h] = b0[h] + sum_e q[e] * Wq[e][h]  (Wq streamed from L2) ----
    if (t < NH1) {
        float acc = b0_g[t];
        #pragma unroll 8
        for (int e = 0; e < NE; e++) acc = fmaf(sQ[e], g_Wq[e * NH1 + t], acc);
        sC[t] = acc;
    }
    // ---- build K' tile: [k, k*q] (float4) ----
    for (int i = t; i < NS * 16; i += 512) {
        int s = i >> 4, e4 = (i & 15) * 4;
        float4 k  = *(const float4*)&keys_g[((size_t)b * NS + s) * NE + e4];
        float4 q4 = *(const float4*)&sQ[e4];
        *(float4*)&sKp[s * NF + e4] = k;
        float4 kq = make_float4(k.x * q4.x, k.y * q4.y, k.z * q4.z, k.w * q4.w);
        *(float4*)&sKp[s * NF + 64 + e4] = kq;
    }
    __syncthreads();

    // ---- GEMM1: H0[s][h] = relu(c[h] + sum_f Kp[s][f] * Wcat[f][h]) ----
    // thread tile: 8 h (4 f32x2 pairs) x 4 s rows; 16 h-groups x 32 s-groups
    {
        const int h_grp = t & 15, s_grp = t >> 4;
        const int h = h_grp * 8;
        unsigned long long acc[4][4];
        int rowoff[4];
        #pragma unroll
        for (int i = 0; i < 4; i++) {
            int s = s_grp + 32 * i; if (s > NS - 1) s = NS - 1;
            rowoff[i] = s * NF;
            #pragma unroll
            for (int p = 0; p < 4; p++)
                acc[i][p] = pack2(sC[h + 2 * p], sC[h + 2 * p + 1]);
        }
        #pragma unroll 1
        for (int f = 0; f < NF; f += 4) {
            float4 a0 = *(const float4*)&sKp[rowoff[0] + f];
            float4 a1 = *(const float4*)&sKp[rowoff[1] + f];
            float4 a2 = *(const float4*)&sKp[rowoff[2] + f];
            float4 a3 = *(const float4*)&sKp[rowoff[3] + f];
            const float* pa0 = (const float*)&a0;
            const float* pa1 = (const float*)&a1;
            const float* pa2 = (const float*)&a2;
            const float* pa3 = (const float*)&a3;
            #pragma unroll
            for (int ff = 0; ff < 4; ff++) {
                const ulonglong2* wp = (const ulonglong2*)&sWcat[(f + ff) * NH1 + h];
                ulonglong2 w01 = wp[0];
                ulonglong2 w23 = wp[1];
                unsigned long long d0 = dup2(pa0[ff]);
                unsigned long long d1 = dup2(pa1[ff]);
                unsigned long long d2 = dup2(pa2[ff]);
                unsigned long long d3 = dup2(pa3[ff]);
                fma2(acc[0][0], d0, w01.x); fma2(acc[0][1], d0, w01.y);
                fma2(acc[0][2], d0, w23.x); fma2(acc[0][3], d0, w23.y);
                fma2(acc[1][0], d1, w01.x); fma2(acc[1][1], d1, w01.y);
                fma2(acc[1][2], d1, w23.x); fma2(acc[1][3], d1, w23.y);
                fma2(acc[2][0], d2, w01.x); fma2(acc[2][1], d2, w01.y);
                fma2(acc[2][2], d2, w23.x); fma2(acc[2][3], d2, w23.y);
                fma2(acc[3][0], d3, w01.x); fma2(acc[3][1], d3, w01.y);
                fma2(acc[3][2], d3, w23.x); fma2(acc[3][3], d3, w23.y);
            }
        }
        #pragma unroll
        for (int i = 0; i < 4; i++) {
            int s = s_grp + 32 * i;
            if (s < NS) {
                float2 v0 = unpack2(acc[i][0]), v1 = unpack2(acc[i][1]);
                float2 v2 = unpack2(acc[i][2]), v3 = unpack2(acc[i][3]);
                float4 o0 = make_float4(fmaxf(v0.x, 0.f), fmaxf(v0.y, 0.f),
                                        fmaxf(v1.x, 0.f), fmaxf(v1.y, 0.f));
                float4 o1 = make_float4(fmaxf(v2.x, 0.f), fmaxf(v2.y, 0.f),
                                        fmaxf(v3.x, 0.f), fmaxf(v3.y, 0.f));
                *(float4*)&sH0[s * NH1 + h]     = o0;
                *(float4*)&sH0[s * NH1 + h + 4] = o1;
            }
        }
    }
    __syncthreads();

    // ---- GEMM2 + fold W2: partial scores directly, H1 never stored ----
    // thread tile: 8 j x 2 s rows; 8 j-groups x 64 s-groups
    {
        const int j_grp = t & 7, s_grp = t >> 3;
        const int j = j_grp * 8;
        const bool row1ok = (s_grp + 64 < NS);
        int rowoff[2];
        rowoff[0] = s_grp * NH1;
        rowoff[1] = (row1ok ? s_grp + 64 : s_grp) * NH1;
        unsigned long long acc[2][4];
        #pragma unroll
        for (int i = 0; i < 2; i++)
            #pragma unroll
            for (int p = 0; p < 4; p++)
                acc[i][p] = pack2(sB1[j + 2 * p], sB1[j + 2 * p + 1]);

        #pragma unroll 1
        for (int hh = 0; hh < NH1; hh += 4) {
            float4 a0 = *(const float4*)&sH0[rowoff[0] + hh];
            float4 a1 = *(const float4*)&sH0[rowoff[1] + hh];
            const float* pa0 = (const float*)&a0;
            const float* pa1 = (const float*)&a1;
            #pragma unroll
            for (int ff = 0; ff < 4; ff++) {
                const ulonglong2* wp = (const ulonglong2*)&sW1[(hh + ff) * NH2 + j];
                ulonglong2 w01 = wp[0];
                ulonglong2 w23 = wp[1];
                unsigned long long d0 = dup2(pa0[ff]);
                unsigned long long d1 = dup2(pa1[ff]);
                fma2(acc[0][0], d0, w01.x); fma2(acc[0][1], d0, w01.y);
                fma2(acc[0][2], d0, w23.x); fma2(acc[0][3], d0, w23.y);
                fma2(acc[1][0], d1, w01.x); fma2(acc[1][1], d1, w01.y);
                fma2(acc[1][2], d1, w23.x); fma2(acc[1][3], d1, w23.y);
            }
        }
        const float w2a = sW2[j],     w2b = sW2[j + 1], w2c = sW2[j + 2], w2d = sW2[j + 3];
        const float w2e = sW2[j + 4], w2f = sW2[j + 5], w2g = sW2[j + 6], w2h = sW2[j + 7];
        #pragma unroll
        for (int i = 0; i < 2; i++) {
            if (i == 1 && !row1ok) break;
            int s = s_grp + 64 * i;
            float2 v0 = unpack2(acc[i][0]), v1 = unpack2(acc[i][1]);
            float2 v2 = unpack2(acc[i][2]), v3 = unpack2(acc[i][3]);
            float p = fmaxf(v0.x, 0.f) * w2a + fmaxf(v0.y, 0.f) * w2b
                    + fmaxf(v1.x, 0.f) * w2c + fmaxf(v1.y, 0.f) * w2d
                    + fmaxf(v2.x, 0.f) * w2e + fmaxf(v2.y, 0.f) * w2f
                    + fmaxf(v3.x, 0.f) * w2g + fmaxf(v3.y, 0.f) * w2h;
            sPart[s * 8 + j_grp] = p;
        }
    }
    __syncthreads();

    // ---- finalize scores ----
    if (t < NS) {
        float sc = b2v;
        #pragma unroll
        for (int g = 0; g < 8; g++) sc += sPart[t * 8 + g];
        sScore[t] = sc;
    }
    __syncthreads();

    // ---- masked softmax over sScore[0..NS) by warp 0 ----
    if (t < 32) {
        float m = -1e30f;
        for (int s = t; s < NS; s += 32) {
            float v = (s < len) ? sScore[s] : -1e30f;
            m = fmaxf(m, v);
        }
        #pragma unroll
        for (int off = 16; off; off >>= 1) m = fmaxf(m, __shfl_xor_sync(0xffffffffu, m, off));
        float sum = 0.f;
        for (int s = t; s < NS; s += 32) {
            float v = (s < len) ? expf(sScore[s] - m) : 0.f;
            sScore[s] = v;
            sum += v;
        }
        #pragma unroll
        for (int off = 16; off; off >>= 1) sum += __shfl_xor_sync(0xffffffffu, sum, off);
        float inv = 1.f / sum;
        for (int s = t; s < NS; s += 32) sScore[s] *= inv;
    }
    __syncthreads();

    // ---- out[e] = sum_s attn[s] * keys[s][e]  (keys = first 64 cols of Kp) ----
    {
        const int e = t & 63, g = t >> 6;   // 8 groups of s
        float acc = 0.f;
        for (int s = g; s < NS; s += 8) acc = fmaf(sScore[s], sKp[s * NF + e], acc);
        sH0[g * 64 + e] = acc;              // H0 reused as scratch
    }
    __syncthreads();
    if (t < 64) {
        float o = 0.f;
        #pragma unroll
        for (int g = 0; g < 8; g++) o += sH0[g * 64 + t];
        out_g[(size_t)b * NE + t] = o;
    }
    if (attn_g && t < NS) attn_g[(size_t)b * NS + t] = sScore[t];
}

extern "C" void kernel_launch(void* const* d_in, const int* in_sizes, int n_in,
                              void* d_out, int out_size) {
    const float* query = (const float*)d_in[0];
    const float* keys  = (const float*)d_in[1];
    const int*   klen  = (const int*)  d_in[2];
    const float* W0    = (const float*)d_in[3];
    const float* b0    = (const float*)d_in[4];
    const float* W1    = (const float*)d_in[5];
    const float* b1    = (const float*)d_in[6];
    const float* W2    = (const float*)d_in[7];
    const float* b2    = (const float*)d_in[8];

    float* outp  = (float*)d_out;
    float* attnp = (out_size >= NB * NE + NB * NS) ? outp + (size_t)NB * NE : nullptr;

    const int smem_bytes = 51400 * (int)sizeof(float);  // 205600 B
    cudaFuncSetAttribute(din_kernel, cudaFuncAttributeMaxDynamicSharedMemorySize,
                         smem_bytes);

    prep_kernel<<<(NF * NH1 + 511) / 512, 512>>>(W0);
    din_kernel<<<NB, 512, smem_bytes>>>(query, keys, klen, b0, W1, b1, W2, b2,
                                        outp, attnp);
}

// round 4
// speedup vs baseline: 1.0015x; 1.0015x over previous
#include <cuda_runtime.h>
#include <cstdint>

#define NB   8192
#define NS   100
#define NE   64
#define NH1  128
#define NH2  64
#define NF   128   // k' = [k, k*q] dimension

// -------- device scratch (alloc-free) --------
__device__ float4 g_Wcat4[(NF * NH1) / 4];  // [f][h]: rows 0..63 = W0b - W0d, rows 64..127 = W0c
__device__ float  g_Wq[NE * NH1];           // [e][h]: W0a + W0d

// -------- f32x2 packed-FMA helpers --------
__device__ __forceinline__ unsigned long long pack2(float lo, float hi) {
    unsigned long long r;
    asm("mov.b64 %0, {%1, %2};" : "=l"(r) : "f"(lo), "f"(hi));
    return r;
}
__device__ __forceinline__ unsigned long long dup2(float v) {
    unsigned long long r;
    asm("mov.b64 %0, {%1, %1};" : "=l"(r) : "f"(v));
    return r;
}
__device__ __forceinline__ void fma2(unsigned long long& d, unsigned long long a,
                                     unsigned long long b) {
    asm("fma.rn.f32x2 %0, %1, %2, %0;" : "+l"(d) : "l"(a), "l"(b));
}
__device__ __forceinline__ float2 unpack2(unsigned long long v) {
    float lo, hi;
    asm("mov.b64 {%0, %1}, %2;" : "=f"(lo), "=f"(hi) : "l"(v));
    return make_float2(lo, hi);
}

// -------- prelude: fold W0 into Wcat / Wq --------
__global__ void prep_kernel(const float* __restrict__ W0) {
    int idx = blockIdx.x * blockDim.x + threadIdx.x;
    if (idx >= NF * NH1) return;
    int e = idx >> 7, h = idx & 127;
    float v;
    if (e < 64) v = W0[(64 + e) * NH1 + h] - W0[(192 + e) * NH1 + h];
    else        v = W0[(128 + (e - 64)) * NH1 + h];
    ((float*)g_Wcat4)[idx] = v;
    if (e < 64) g_Wq[idx] = W0[e * NH1 + h] + W0[(192 + e) * NH1 + h];
}

// -------- fused per-batch kernel: 1 CTA = 1 batch, 512 threads --------
// smem (floats): sWcat 16384 | sW1 8192 | sKp 12800 | sH0 12800 |
//                sC 128 | sQ 64 | sW2 64 | sB1 64 | sScore 104 | sPart 800
//                = 51400 floats = 205600 B
__global__ __launch_bounds__(512, 1)
void din_kernel(const float* __restrict__ q_g,
                const float* __restrict__ keys_g,
                const int*   __restrict__ klen_g,
                const float* __restrict__ b0_g,
                const float* __restrict__ W1_g,
                const float* __restrict__ b1_g,
                const float* __restrict__ W2_g,
                const float* __restrict__ b2_g,
                float* __restrict__ out_g,
                float* __restrict__ attn_g) {
    extern __shared__ float sm[];
    float* sWcat  = sm;                 // 16384
    float* sW1    = sWcat + 16384;      // 8192
    float* sKp    = sW1 + 8192;         // 12800  [s][f]  (f<64 = keys row)
    float* sH0    = sKp + 12800;        // 12800  [s][h]
    float* sC     = sH0 + 12800;        // 128
    float* sQ     = sC + 128;           // 64
    float* sW2    = sQ + 64;            // 64
    float* sB1    = sW2 + 64;           // 64
    float* sScore = sB1 + 64;           // 104
    float* sPart  = sScore + 104;       // 800

    const int b = blockIdx.x;
    const int t = threadIdx.x;
    const int len = klen_g[b];
    const float b2v = b2_g[0];

    // ---- load shared weights + q (vectorized) ----
    {
        float4* dw = (float4*)sWcat;
        for (int i = t; i < (NF * NH1) / 4; i += 512) dw[i] = g_Wcat4[i];
        const float4* gw1 = (const float4*)W1_g;
        float4* dw1 = (float4*)sW1;
        for (int i = t; i < (NH1 * NH2) / 4; i += 512) dw1[i] = gw1[i];
        if (t < 64) { sQ[t] = q_g[b * NE + t]; sW2[t] = W2_g[t]; sB1[t] = b1_g[t]; }
    }
    __syncthreads();

    // ---- c[h] = b0[h] + sum_e q[e] * Wq[e][h]  (Wq streamed from L2) ----
    if (t < NH1) {
        float acc = b0_g[t];
        #pragma unroll 8
        for (int e = 0; e < NE; e++) acc = fmaf(sQ[e], g_Wq[e * NH1 + t], acc);
        sC[t] = acc;
    }
    // ---- build K' tile: [k, k*q] (float4) ----
    for (int i = t; i < NS * 16; i += 512) {
        int s = i >> 4, e4 = (i & 15) * 4;
        float4 k  = *(const float4*)&keys_g[((size_t)b * NS + s) * NE + e4];
        float4 q4 = *(const float4*)&sQ[e4];
        *(float4*)&sKp[s * NF + e4] = k;
        float4 kq = make_float4(k.x * q4.x, k.y * q4.y, k.z * q4.z, k.w * q4.w);
        *(float4*)&sKp[s * NF + 64 + e4] = kq;
    }
    __syncthreads();

    // ---- GEMM1: H0[s][h] = relu(c[h] + sum_f Kp[s][f] * Wcat[f][h]) ----
    // thread tile: 8 h (4 f32x2 pairs) x 4 s rows; 16 h-groups x 32 s-groups
    {
        const int h_grp = t & 15, s_grp = t >> 4;
        const int h = h_grp * 8;
        unsigned long long acc[4][4];
        int rowoff[4];
        #pragma unroll
        for (int i = 0; i < 4; i++) {
            int s = s_grp + 32 * i; if (s > NS - 1) s = NS - 1;
            rowoff[i] = s * NF;
            #pragma unroll
            for (int p = 0; p < 4; p++)
                acc[i][p] = pack2(sC[h + 2 * p], sC[h + 2 * p + 1]);
        }
        #pragma unroll 1
        for (int f = 0; f < NF; f += 4) {
            float4 a0 = *(const float4*)&sKp[rowoff[0] + f];
            float4 a1 = *(const float4*)&sKp[rowoff[1] + f];
            float4 a2 = *(const float4*)&sKp[rowoff[2] + f];
            float4 a3 = *(const float4*)&sKp[rowoff[3] + f];
            const float* pa0 = (const float*)&a0;
            const float* pa1 = (const float*)&a1;
            const float* pa2 = (const float*)&a2;
            const float* pa3 = (const float*)&a3;
            #pragma unroll
            for (int ff = 0; ff < 4; ff++) {
                const ulonglong2* wp = (const ulonglong2*)&sWcat[(f + ff) * NH1 + h];
                ulonglong2 w01 = wp[0];
                ulonglong2 w23 = wp[1];
                unsigned long long d0 = dup2(pa0[ff]);
                unsigned long long d1 = dup2(pa1[ff]);
                unsigned long long d2 = dup2(pa2[ff]);
                unsigned long long d3 = dup2(pa3[ff]);
                fma2(acc[0][0], d0, w01.x); fma2(acc[0][1], d0, w01.y);
                fma2(acc[0][2], d0, w23.x); fma2(acc[0][3], d0, w23.y);
                fma2(acc[1][0], d1, w01.x); fma2(acc[1][1], d1, w01.y);
                fma2(acc[1][2], d1, w23.x); fma2(acc[1][3], d1, w23.y);
                fma2(acc[2][0], d2, w01.x); fma2(acc[2][1], d2, w01.y);
                fma2(acc[2][2], d2, w23.x); fma2(acc[2][3], d2, w23.y);
                fma2(acc[3][0], d3, w01.x); fma2(acc[3][1], d3, w01.y);
                fma2(acc[3][2], d3, w23.x); fma2(acc[3][3], d3, w23.y);
            }
        }
        #pragma unroll
        for (int i = 0; i < 4; i++) {
            int s = s_grp + 32 * i;
            if (s < NS) {
                float2 v0 = unpack2(acc[i][0]), v1 = unpack2(acc[i][1]);
                float2 v2 = unpack2(acc[i][2]), v3 = unpack2(acc[i][3]);
                float4 o0 = make_float4(fmaxf(v0.x, 0.f), fmaxf(v0.y, 0.f),
                                        fmaxf(v1.x, 0.f), fmaxf(v1.y, 0.f));
                float4 o1 = make_float4(fmaxf(v2.x, 0.f), fmaxf(v2.y, 0.f),
                                        fmaxf(v3.x, 0.f), fmaxf(v3.y, 0.f));
                *(float4*)&sH0[s * NH1 + h]     = o0;
                *(float4*)&sH0[s * NH1 + h + 4] = o1;
            }
        }
    }
    __syncthreads();

    // ---- GEMM2 + fold W2: partial scores directly, H1 never stored ----
    // thread tile: 8 j x 2 s rows; 8 j-groups x 64 s-groups
    {
        const int j_grp = t & 7, s_grp = t >> 3;
        const int j = j_grp * 8;
        const bool row1ok = (s_grp + 64 < NS);
        int rowoff[2];
        rowoff[0] = s_grp * NH1;
        rowoff[1] = (row1ok ? s_grp + 64 : s_grp) * NH1;
        unsigned long long acc[2][4];
        #pragma unroll
        for (int i = 0; i < 2; i++)
            #pragma unroll
            for (int p = 0; p < 4; p++)
                acc[i][p] = pack2(sB1[j + 2 * p], sB1[j + 2 * p + 1]);

        #pragma unroll 1
        for (int hh = 0; hh < NH1; hh += 4) {
            float4 a0 = *(const float4*)&sH0[rowoff[0] + hh];
            float4 a1 = *(const float4*)&sH0[rowoff[1] + hh];
            const float* pa0 = (const float*)&a0;
            const float* pa1 = (const float*)&a1;
            #pragma unroll
            for (int ff = 0; ff < 4; ff++) {
                const ulonglong2* wp = (const ulonglong2*)&sW1[(hh + ff) * NH2 + j];
                ulonglong2 w01 = wp[0];
                ulonglong2 w23 = wp[1];
                unsigned long long d0 = dup2(pa0[ff]);
                unsigned long long d1 = dup2(pa1[ff]);
                fma2(acc[0][0], d0, w01.x); fma2(acc[0][1], d0, w01.y);
                fma2(acc[0][2], d0, w23.x); fma2(acc[0][3], d0, w23.y);
                fma2(acc[1][0], d1, w01.x); fma2(acc[1][1], d1, w01.y);
                fma2(acc[1][2], d1, w23.x); fma2(acc[1][3], d1, w23.y);
            }
        }
        const float w2a = sW2[j],     w2b = sW2[j + 1], w2c = sW2[j + 2], w2d = sW2[j + 3];
        const float w2e = sW2[j + 4], w2f = sW2[j + 5], w2g = sW2[j + 6], w2h = sW2[j + 7];
        #pragma unroll
        for (int i = 0; i < 2; i++) {
            if (i == 1 && !row1ok) break;
            int s = s_grp + 64 * i;
            float2 v0 = unpack2(acc[i][0]), v1 = unpack2(acc[i][1]);
            float2 v2 = unpack2(acc[i][2]), v3 = unpack2(acc[i][3]);
            float p = fmaxf(v0.x, 0.f) * w2a + fmaxf(v0.y, 0.f) * w2b
                    + fmaxf(v1.x, 0.f) * w2c + fmaxf(v1.y, 0.f) * w2d
                    + fmaxf(v2.x, 0.f) * w2e + fmaxf(v2.y, 0.f) * w2f
                    + fmaxf(v3.x, 0.f) * w2g + fmaxf(v3.y, 0.f) * w2h;
            sPart[s * 8 + j_grp] = p;
        }
    }
    __syncthreads();

    // ---- finalize scores ----
    if (t < NS) {
        float sc = b2v;
        #pragma unroll
        for (int g = 0; g < 8; g++) sc += sPart[t * 8 + g];
        sScore[t] = sc;
    }
    __syncthreads();

    // ---- masked softmax over sScore[0..NS) by warp 0 ----
    if (t < 32) {
        float m = -1e30f;
        for (int s = t; s < NS; s += 32) {
            float v = (s < len) ? sScore[s] : -1e30f;
            m = fmaxf(m, v);
        }
        #pragma unroll
        for (int off = 16; off; off >>= 1) m = fmaxf(m, __shfl_xor_sync(0xffffffffu, m, off));
        float sum = 0.f;
        for (int s = t; s < NS; s += 32) {
            float v = (s < len) ? expf(sScore[s] - m) : 0.f;
            sScore[s] = v;
            sum += v;
        }
        #pragma unroll
        for (int off = 16; off; off >>= 1) sum += __shfl_xor_sync(0xffffffffu, sum, off);
        float inv = 1.f / sum;
        for (int s = t; s < NS; s += 32) sScore[s] *= inv;
    }
    __syncthreads();

    // ---- out[e] = sum_s attn[s] * keys[s][e]  (keys = first 64 cols of Kp) ----
    {
        const int e = t & 63, g = t >> 6;   // 8 groups of s
        float acc = 0.f;
        for (int s = g; s < NS; s += 8) acc = fmaf(sScore[s], sKp[s * NF + e], acc);
        sH0[g * 64 + e] = acc;              // H0 reused as scratch
    }
    __syncthreads();
    if (t < 64) {
        float o = 0.f;
        #pragma unroll
        for (int g = 0; g < 8; g++) o += sH0[g * 64 + t];
        out_g[(size_t)b * NE + t] = o;
    }
    if (attn_g && t < NS) attn_g[(size_t)b * NS + t] = sScore[t];
}

extern "C" void kernel_launch(void* const* d_in, const int* in_sizes, int n_in,
                              void* d_out, int out_size) {
    const float* query = (const float*)d_in[0];
    const float* keys  = (const float*)d_in[1];
    const int*   klen  = (const int*)  d_in[2];
    const float* W0    = (const float*)d_in[3];
    const float* b0    = (const float*)d_in[4];
    const float* W1    = (const float*)d_in[5];
    const float* b1    = (const float*)d_in[6];
    const float* W2    = (const float*)d_in[7];
    const float* b2    = (const float*)d_in[8];

    float* outp  = (float*)d_out;
    float* attnp = (out_size >= NB * NE + NB * NS) ? outp + (size_t)NB * NE : nullptr;

    const int smem_bytes = 51400 * (int)sizeof(float);  // 205600 B
    cudaFuncSetAttribute(din_kernel, cudaFuncAttributeMaxDynamicSharedMemorySize,
                         smem_bytes);

    prep_kernel<<<(NF * NH1 + 511) / 512, 512>>>(W0);
    din_kernel<<<NB, 512, smem_bytes>>>(query, keys, klen, b0, W1, b1, W2, b2,
                                        outp, attnp);
}

// round 6
// speedup vs baseline: 2.5287x; 2.5249x over previous
#include <cuda_runtime.h>
#include <cuda_bf16.h>
#include <cstdint>

#define NB   8192
#define NS   100
#define NE   64
#define NH1  128
#define NH2  64
#define NF   128

#define ASTRIDE 272                 // padded bf16 row stride in bytes (128*2 + 16)
#define A_BYTES (128 * ASTRIDE)     // 34816
#define B2_BYTES (64 * ASTRIDE)     // 17408

// ---- smem byte offsets ----
#define OFF_AH    0                    // A hi  (Kp, later H0)
#define OFF_AL    (OFF_AH + A_BYTES)   // A lo
#define OFF_B1H   (OFF_AL + A_BYTES)   // Wcat^T hi [128h][128f]
#define OFF_B1L   (OFF_B1H + A_BYTES)
#define OFF_B2H   (OFF_B1L + A_BYTES)  // W1^T hi [64j][128h]
#define OFF_B2L   (OFF_B2H + B2_BYTES)
#define OFF_C     (OFF_B2L + B2_BYTES) // c[128] f32
#define OFF_Q     (OFF_C + 512)
#define OFF_W2    (OFF_Q + 256)
#define OFF_B1B   (OFF_W2 + 256)
#define OFF_SCORE (OFF_B1B + 256)      // 128 f32
#define OFF_PART  (OFF_SCORE + 512)    // 128*2 f32
#define OFF_POUT  (OFF_PART + 1024)    // 4*64 f32
#define SMEM_TOTAL (OFF_POUT + 1024)   // = 177920 B

// ---- device scratch: pre-split weights, [n][k] bf16, 136-elem row stride ----
__device__ __nv_bfloat16 g_B1[2][128 * 136];
__device__ __nv_bfloat16 g_B2[2][64 * 136];
__device__ float g_Wq[NE * NH1];    // [e][h] = W0a + W0d

// ================= helpers =================
__device__ __forceinline__ uint32_t smem_u32(const void* p) {
    uint32_t a;
    asm("{ .reg .u64 t; cvta.to.shared.u64 t, %1; cvt.u32.u64 %0, t; }" : "=r"(a) : "l"(p));
    return a;
}
__device__ __forceinline__ void ldsm4(uint32_t* r, uint32_t addr) {
    asm volatile("ldmatrix.sync.aligned.m8n8.x4.shared.b16 {%0,%1,%2,%3}, [%4];"
                 : "=r"(r[0]), "=r"(r[1]), "=r"(r[2]), "=r"(r[3]) : "r"(addr));
}
__device__ __forceinline__ void mma_bf16(float* c, const uint32_t* a, uint32_t b0, uint32_t b1) {
    asm volatile("mma.sync.aligned.m16n8k16.row.col.f32.bf16.bf16.f32 "
                 "{%0,%1,%2,%3}, {%4,%5,%6,%7}, {%8,%9}, {%0,%1,%2,%3};"
                 : "+f"(c[0]), "+f"(c[1]), "+f"(c[2]), "+f"(c[3])
                 : "r"(a[0]), "r"(a[1]), "r"(a[2]), "r"(a[3]), "r"(b0), "r"(b1));
}
// pack (lo -> lower half, hi -> upper half)
__device__ __forceinline__ uint32_t cvt_bf16x2(float lo, float hi) {
    uint32_t r;
    asm("cvt.rn.bf16x2.f32 %0, %1, %2;" : "=r"(r) : "f"(hi), "f"(lo));
    return r;
}
__device__ __forceinline__ void split_pair(float x0, float x1, uint32_t& hi2, uint32_t& lo2) {
    hi2 = cvt_bf16x2(x0, x1);
    float h0 = __uint_as_float(hi2 << 16);
    float h1 = __uint_as_float(hi2 & 0xffff0000u);
    lo2 = cvt_bf16x2(x0 - h0, x1 - h1);
}

// ================= prep: fold + split weights =================
__global__ void prep_kernel(const float* __restrict__ W0, const float* __restrict__ W1) {
    int gid = blockIdx.x * blockDim.x + threadIdx.x;
    if (gid < 16384) {                 // B1: n=h, k=f -> Wcat[f][h]
        int n = gid >> 7, k = gid & 127;
        float v;
        if (k < 64) v = W0[(64 + k) * NH1 + n] - W0[(192 + k) * NH1 + n];
        else        v = W0[(128 + (k - 64)) * NH1 + n];
        __nv_bfloat16 h = __float2bfloat16(v);
        g_B1[0][n * 136 + k] = h;
        g_B1[1][n * 136 + k] = __float2bfloat16(v - __bfloat162float(h));
    } else if (gid < 24576) {          // B2: n=j, k=h -> W1[h][j]
        int i = gid - 16384;
        int n = i >> 7, k = i & 127;
        float v = W1[k * NH2 + n];
        __nv_bfloat16 h = __float2bfloat16(v);
        g_B2[0][n * 136 + k] = h;
        g_B2[1][n * 136 + k] = __float2bfloat16(v - __bfloat162float(h));
    } else if (gid < 32768) {          // Wq = W0a + W0d
        int i = gid - 24576;
        int e = i >> 7, hh = i & 127;
        g_Wq[e * NH1 + hh] = W0[e * NH1 + hh] + W0[(192 + e) * NH1 + hh];
    }
}

// ================= fused kernel: 1 CTA = 1 batch, 256 threads =================
__global__ __launch_bounds__(256, 1)
void din_kernel(const float* __restrict__ q_g,
                const float* __restrict__ keys_g,
                const int*   __restrict__ klen_g,
                const float* __restrict__ b0_g,
                const float* __restrict__ b1_g,
                const float* __restrict__ W2_g,
                const float* __restrict__ b2_g,
                float* __restrict__ out_g,
                float* __restrict__ attn_g) {
    extern __shared__ char smem[];
    const uint32_t sbase = smem_u32(smem);
    float* sC     = (float*)(smem + OFF_C);
    float* sQ     = (float*)(smem + OFF_Q);
    float* sW2    = (float*)(smem + OFF_W2);
    float* sB1b   = (float*)(smem + OFF_B1B);
    float* sScore = (float*)(smem + OFF_SCORE);
    float* sPart  = (float*)(smem + OFF_PART);
    float* sPOut  = (float*)(smem + OFF_POUT);

    const int b = blockIdx.x;
    const int t = threadIdx.x;
    const int lane = t & 31, w = t >> 5;
    const int len = klen_g[b];
    const float b2v = b2_g[0];

    // ---- weight tiles -> smem (straight uint4 copies, L2-hot) ----
    {
        const uint4* s1 = (const uint4*)&g_B1[0][0];
        uint4* d1 = (uint4*)(smem + OFF_B1H);
        #pragma unroll 4
        for (int i = t; i < (2 * A_BYTES) / 16; i += 256) d1[i] = s1[i];
        const uint4* s2 = (const uint4*)&g_B2[0][0];
        uint4* d2 = (uint4*)(smem + OFF_B2H);
        #pragma unroll 4
        for (int i = t; i < (2 * B2_BYTES) / 16; i += 256) d2[i] = s2[i];
    }
    if (t < 64) { sQ[t] = q_g[b * NE + t]; sW2[t] = W2_g[t]; sB1b[t] = b1_g[t]; }
    __syncthreads();   // sQ ready for Kp build

    // ---- c[h] = b0[h] + sum_e q[e] * Wq[e][h] ----
    if (t < NH1) {
        float acc = b0_g[t];
        #pragma unroll 8
        for (int e = 0; e < NE; e++) acc = fmaf(sQ[e], g_Wq[e * NH1 + t], acc);
        sC[t] = acc;
    }

    // ---- A1 = [keys | keys*q] bf16 hi/lo into padded smem ----
    for (int i = t; i < NS * 32; i += 256) {
        int s = i >> 5, p = i & 31;           // element pair (2p, 2p+1)
        float2 kv = *(const float2*)&keys_g[((size_t)b * NS + s) * NE + 2 * p];
        uint32_t hi, lo;
        split_pair(kv.x, kv.y, hi, lo);
        *(uint32_t*)(smem + OFF_AH + s * ASTRIDE + p * 4) = hi;
        *(uint32_t*)(smem + OFF_AL + s * ASTRIDE + p * 4) = lo;
        float q0 = sQ[2 * p], q1 = sQ[2 * p + 1];
        split_pair(kv.x * q0, kv.y * q1, hi, lo);
        *(uint32_t*)(smem + OFF_AH + s * ASTRIDE + 128 + p * 4) = hi;
        *(uint32_t*)(smem + OFF_AL + s * ASTRIDE + 128 + p * 4) = lo;
    }
    // zero pad rows 100..127 (both hi and lo)
    for (int i = t; i < 28 * 17 * 2; i += 256) {
        int m = i / (28 * 17), r = (i % (28 * 17)) / 17, cc = i % 17;
        *(uint4*)(smem + (m ? OFF_AL : OFF_AH) + (100 + r) * ASTRIDE + cc * 16) =
            make_uint4(0, 0, 0, 0);
    }
    __syncthreads();

    // ---- lane geometry for ldmatrix ----
    const uint32_t aRow = lane & 15;
    const uint32_t aCol = ((lane >> 4) & 1) * 16;           // bytes
    const uint32_t bRow = (lane & 7) + ((lane >> 4) & 1) * 8;
    const uint32_t bCol = ((lane >> 3) & 1) * 16;           // bytes

    const int mg = w >> 1, s0 = mg * 32;
    const uint32_t aBaseH0 = sbase + OFF_AH + (s0 + aRow) * ASTRIDE + aCol;
    const uint32_t aBaseH1 = aBaseH0 + 16 * ASTRIDE;
    const uint32_t aBaseL0 = aBaseH0 + A_BYTES;
    const uint32_t aBaseL1 = aBaseH1 + A_BYTES;

    // ================= GEMM1: D1[128s x 128h] = Kp @ Wcat =================
    float acc[16][4];
    {
        const int ng = w & 1, h0 = ng * 64;
        #pragma unroll
        for (int i = 0; i < 16; i++)
            #pragma unroll
            for (int j = 0; j < 4; j++) acc[i][j] = 0.f;

        uint32_t bBaseH[4], bBaseL[4];
        #pragma unroll
        for (int np = 0; np < 4; np++) {
            bBaseH[np] = sbase + OFF_B1H + (h0 + np * 16 + bRow) * ASTRIDE + bCol;
            bBaseL[np] = bBaseH[np] + A_BYTES;
        }

        #pragma unroll
        for (int k = 0; k < 8; k++) {
            const uint32_t ko = k * 32;
            uint32_t ah0[4], ah1[4], al0[4], al1[4];
            ldsm4(ah0, aBaseH0 + ko);
            ldsm4(ah1, aBaseH1 + ko);
            ldsm4(al0, aBaseL0 + ko);
            ldsm4(al1, aBaseL1 + ko);
            uint32_t bh[4][4], bl[4][4];
            #pragma unroll
            for (int np = 0; np < 4; np++) {
                ldsm4(bh[np], bBaseH[np] + ko);
                ldsm4(bl[np], bBaseL[np] + ko);
            }
            #pragma unroll
            for (int np = 0; np < 4; np++) {
                #pragma unroll
                for (int half = 0; half < 2; half++) {
                    const int nt = np * 2 + half;
                    const uint32_t bh0 = bh[np][half * 2], bh1 = bh[np][half * 2 + 1];
                    const uint32_t bl0 = bl[np][half * 2], bl1 = bl[np][half * 2 + 1];
                    mma_bf16(acc[nt],     ah0, bh0, bh1);
                    mma_bf16(acc[nt],     ah0, bl0, bl1);
                    mma_bf16(acc[nt],     al0, bh0, bh1);
                    mma_bf16(acc[8 + nt], ah1, bh0, bh1);
                    mma_bf16(acc[8 + nt], ah1, bl0, bl1);
                    mma_bf16(acc[8 + nt], al1, bh0, bh1);
                }
            }
        }
    }
    __syncthreads();   // done reading A1

    // ---- epilogue1: H0 = relu(D1 + c) -> split bf16 -> A region ----
    {
        const int ng = w & 1, h0 = ng * 64;
        #pragma unroll
        for (int mt = 0; mt < 2; mt++) {
            #pragma unroll
            for (int nt = 0; nt < 8; nt++) {
                const float* c = acc[mt * 8 + nt];
                const int row = s0 + mt * 16 + (lane >> 2);
                const int col = h0 + nt * 8 + (lane & 3) * 2;
                const float c0 = sC[col], c1 = sC[col + 1];
                uint32_t hi, lo;
                split_pair(fmaxf(c[0] + c0, 0.f), fmaxf(c[1] + c1, 0.f), hi, lo);
                *(uint32_t*)(smem + OFF_AH + row * ASTRIDE + col * 2) = hi;
                *(uint32_t*)(smem + OFF_AL + row * ASTRIDE + col * 2) = lo;
                split_pair(fmaxf(c[2] + c0, 0.f), fmaxf(c[3] + c1, 0.f), hi, lo);
                *(uint32_t*)(smem + OFF_AH + (row + 8) * ASTRIDE + col * 2) = hi;
                *(uint32_t*)(smem + OFF_AL + (row + 8) * ASTRIDE + col * 2) = lo;
            }
        }
    }
    __syncthreads();

    // ================= GEMM2: D2[128s x 64j] = H0 @ W1 =================
    float acc2[8][4];
    const int ng2 = w & 1, j0 = ng2 * 32;
    {
        #pragma unroll
        for (int i = 0; i < 8; i++)
            #pragma unroll
            for (int j = 0; j < 4; j++) acc2[i][j] = 0.f;

        uint32_t bBaseH[2], bBaseL[2];
        #pragma unroll
        for (int np = 0; np < 2; np++) {
            bBaseH[np] = sbase + OFF_B2H + (j0 + np * 16 + bRow) * ASTRIDE + bCol;
            bBaseL[np] = bBaseH[np] + B2_BYTES;
        }

        #pragma unroll
        for (int k = 0; k < 8; k++) {
            const uint32_t ko = k * 32;
            uint32_t ah0[4], ah1[4], al0[4], al1[4];
            ldsm4(ah0, aBaseH0 + ko);
            ldsm4(ah1, aBaseH1 + ko);
            ldsm4(al0, aBaseL0 + ko);
            ldsm4(al1, aBaseL1 + ko);
            uint32_t bh[2][4], bl[2][4];
            #pragma unroll
            for (int np = 0; np < 2; np++) {
                ldsm4(bh[np], bBaseH[np] + ko);
                ldsm4(bl[np], bBaseL[np] + ko);
            }
            #pragma unroll
            for (int np = 0; np < 2; np++) {
                #pragma unroll
                for (int half = 0; half < 2; half++) {
                    const int nt = np * 2 + half;
                    const uint32_t bh0 = bh[np][half * 2], bh1 = bh[np][half * 2 + 1];
                    const uint32_t bl0 = bl[np][half * 2], bl1 = bl[np][half * 2 + 1];
                    mma_bf16(acc2[nt],     ah0, bh0, bh1);
                    mma_bf16(acc2[nt],     ah0, bl0, bl1);
                    mma_bf16(acc2[nt],     al0, bh0, bh1);
                    mma_bf16(acc2[4 + nt], ah1, bh0, bh1);
                    mma_bf16(acc2[4 + nt], ah1, bl0, bl1);
                    mma_bf16(acc2[4 + nt], al1, bh0, bh1);
                }
            }
        }
    }

    // ---- epilogue2: scores = sum_j relu(D2 + b1)*W2 ----
    {
        float part[4] = {0.f, 0.f, 0.f, 0.f};   // [mt][rowhalf]
        #pragma unroll
        for (int mt = 0; mt < 2; mt++) {
            #pragma unroll
            for (int nt = 0; nt < 4; nt++) {
                const float* c = acc2[mt * 4 + nt];
                const int col = j0 + nt * 8 + (lane & 3) * 2;
                const float bb0 = sB1b[col], bb1 = sB1b[col + 1];
                const float w0v = sW2[col],  w1v = sW2[col + 1];
                part[mt * 2]     += fmaxf(c[0] + bb0, 0.f) * w0v + fmaxf(c[1] + bb1, 0.f) * w1v;
                part[mt * 2 + 1] += fmaxf(c[2] + bb0, 0.f) * w0v + fmaxf(c[3] + bb1, 0.f) * w1v;
            }
        }
        #pragma unroll
        for (int i = 0; i < 4; i++) {
            float v = part[i];
            v += __shfl_xor_sync(0xffffffffu, v, 1);
            v += __shfl_xor_sync(0xffffffffu, v, 2);
            if ((lane & 3) == 0) {
                const int row = s0 + (i >> 1) * 16 + (lane >> 2) + (i & 1) * 8;
                sPart[row * 2 + ng2] = v;
            }
        }
    }
    __syncthreads();
    if (t < 128) sScore[t] = sPart[t * 2] + sPart[t * 2 + 1] + b2v;
    __syncthreads();

    // ---- masked softmax (warp 0) ----
    if (t < 32) {
        float m = -1e30f;
        for (int s = t; s < NS; s += 32) {
            float v = (s < len) ? sScore[s] : -1e30f;
            m = fmaxf(m, v);
        }
        #pragma unroll
        for (int off = 16; off; off >>= 1) m = fmaxf(m, __shfl_xor_sync(0xffffffffu, m, off));
        float sum = 0.f;
        for (int s = t; s < NS; s += 32) {
            float v = (s < len) ? expf(sScore[s] - m) : 0.f;
            sScore[s] = v;
            sum += v;
        }
        #pragma unroll
        for (int off = 16; off; off >>= 1) sum += __shfl_xor_sync(0xffffffffu, sum, off);
        float inv = 1.f / sum;
        for (int s = t; s < NS; s += 32) sScore[s] *= inv;
    }
    __syncthreads();

    // ---- out[e] = sum_s attn[s] * keys[s][e] (keys L2-hot) ----
    {
        const int e = t & 63, g = t >> 6;
        const float* kb = keys_g + (size_t)b * NS * NE;
        float a = 0.f;
        for (int s = g; s < NS; s += 4) a = fmaf(sScore[s], kb[s * NE + e], a);
        sPOut[g * 64 + e] = a;
    }
    __syncthreads();
    if (t < 64)
        out_g[(size_t)b * NE + t] = sPOut[t] + sPOut[64 + t] + sPOut[128 + t] + sPOut[192 + t];
    if (attn_g && t < NS) attn_g[(size_t)b * NS + t] = sScore[t];
}

extern "C" void kernel_launch(void* const* d_in, const int* in_sizes, int n_in,
                              void* d_out, int out_size) {
    const float* query = (const float*)d_in[0];
    const float* keys  = (const float*)d_in[1];
    const int*   klen  = (const int*)  d_in[2];
    const float* W0    = (const float*)d_in[3];
    const float* b0    = (const float*)d_in[4];
    const float* W1    = (const float*)d_in[5];
    const float* b1    = (const float*)d_in[6];
    const float* W2    = (const float*)d_in[7];
    const float* b2    = (const float*)d_in[8];

    float* outp  = (float*)d_out;
    float* attnp = (out_size >= NB * NE + NB * NS) ? outp + (size_t)NB * NE : nullptr;

    cudaFuncSetAttribute(din_kernel, cudaFuncAttributeMaxDynamicSharedMemorySize, SMEM_TOTAL);

    prep_kernel<<<64, 512>>>(W0, W1);
    din_kernel<<<NB, 256, SMEM_TOTAL>>>(query, keys, klen, b0, b1, W2, b2, outp, attnp);
}

// round 7
// speedup vs baseline: 2.5533x; 1.0097x over previous
#include <cuda_runtime.h>
#include <cuda_bf16.h>
#include <cstdint>

#define NB   8192
#define NS   100
#define NE   64
#define NH1  128
#define NH2  64
#define NF   128

#define ASTRIDE 272                 // padded bf16 row stride in bytes (128*2 + 16)
#define A_BYTES (128 * ASTRIDE)     // 34816
#define B2_BYTES (64 * ASTRIDE)     // 17408

// ---- smem byte offsets ----
#define OFF_AH    0                    // A hi  (Kp, later H0)
#define OFF_AL    (OFF_AH + A_BYTES)   // A lo
#define OFF_B1H   (OFF_AL + A_BYTES)   // Wcat^T hi [128h][128f]
#define OFF_B1L   (OFF_B1H + A_BYTES)
#define OFF_B2H   (OFF_B1L + A_BYTES)  // W1^T hi [64j][128h]
#define OFF_B2L   (OFF_B2H + B2_BYTES)
#define OFF_C     (OFF_B2L + B2_BYTES) // c[128] f32
#define OFF_Q     (OFF_C + 512)
#define OFF_W2    (OFF_Q + 256)
#define OFF_B1B   (OFF_W2 + 256)
#define OFF_SCORE (OFF_B1B + 256)      // 128 f32
#define OFF_PART  (OFF_SCORE + 512)    // 128*2 f32
#define OFF_POUT  (OFF_PART + 1024)    // 4*64 f32
#define SMEM_TOTAL (OFF_POUT + 1024)   // = 177920 B

// ---- device scratch: pre-split weights, [n][k] bf16, 136-elem row stride ----
__device__ __nv_bfloat16 g_B1[2][128 * 136];
__device__ __nv_bfloat16 g_B2[2][64 * 136];
__device__ float g_Wq[NE * NH1];    // [e][h] = W0a + W0d

// ================= helpers =================
__device__ __forceinline__ uint32_t smem_u32(const void* p) {
    uint32_t a;
    asm("{ .reg .u64 t; cvta.to.shared.u64 t, %1; cvt.u32.u64 %0, t; }" : "=r"(a) : "l"(p));
    return a;
}
__device__ __forceinline__ void ldsm4(uint32_t* r, uint32_t addr) {
    asm volatile("ldmatrix.sync.aligned.m8n8.x4.shared.b16 {%0,%1,%2,%3}, [%4];"
                 : "=r"(r[0]), "=r"(r[1]), "=r"(r[2]), "=r"(r[3]) : "r"(addr));
}
__device__ __forceinline__ void mma_bf16(float* c, const uint32_t* a, uint32_t b0, uint32_t b1) {
    asm volatile("mma.sync.aligned.m16n8k16.row.col.f32.bf16.bf16.f32 "
                 "{%0,%1,%2,%3}, {%4,%5,%6,%7}, {%8,%9}, {%0,%1,%2,%3};"
                 : "+f"(c[0]), "+f"(c[1]), "+f"(c[2]), "+f"(c[3])
                 : "r"(a[0]), "r"(a[1]), "r"(a[2]), "r"(a[3]), "r"(b0), "r"(b1));
}
// pack (lo -> lower half, hi -> upper half)
__device__ __forceinline__ uint32_t cvt_bf16x2(float lo, float hi) {
    uint32_t r;
    asm("cvt.rn.bf16x2.f32 %0, %1, %2;" : "=r"(r) : "f"(hi), "f"(lo));
    return r;
}
__device__ __forceinline__ void split_pair(float x0, float x1, uint32_t& hi2, uint32_t& lo2) {
    hi2 = cvt_bf16x2(x0, x1);
    float h0 = __uint_as_float(hi2 << 16);
    float h1 = __uint_as_float(hi2 & 0xffff0000u);
    lo2 = cvt_bf16x2(x0 - h0, x1 - h1);
}

// ================= prep: fold + split weights =================
__global__ void prep_kernel(const float* __restrict__ W0, const float* __restrict__ W1) {
    int gid = blockIdx.x * blockDim.x + threadIdx.x;
    if (gid < 16384) {                 // B1: n=h, k=f -> Wcat[f][h]
        int n = gid >> 7, k = gid & 127;
        float v;
        if (k < 64) v = W0[(64 + k) * NH1 + n] - W0[(192 + k) * NH1 + n];
        else        v = W0[(128 + (k - 64)) * NH1 + n];
        __nv_bfloat16 h = __float2bfloat16(v);
        g_B1[0][n * 136 + k] = h;
        g_B1[1][n * 136 + k] = __float2bfloat16(v - __bfloat162float(h));
    } else if (gid < 24576) {          // B2: n=j, k=h -> W1[h][j]
        int i = gid - 16384;
        int n = i >> 7, k = i & 127;
        float v = W1[k * NH2 + n];
        __nv_bfloat16 h = __float2bfloat16(v);
        g_B2[0][n * 136 + k] = h;
        g_B2[1][n * 136 + k] = __float2bfloat16(v - __bfloat162float(h));
    } else if (gid < 32768) {          // Wq = W0a + W0d
        int i = gid - 24576;
        int e = i >> 7, hh = i & 127;
        g_Wq[e * NH1 + hh] = W0[e * NH1 + hh] + W0[(192 + e) * NH1 + hh];
    }
}

// ================= fused kernel: 1 CTA = 1 batch, 256 threads =================
__global__ __launch_bounds__(256, 1)
void din_kernel(const float* __restrict__ q_g,
                const float* __restrict__ keys_g,
                const int*   __restrict__ klen_g,
                const float* __restrict__ b0_g,
                const float* __restrict__ b1_g,
                const float* __restrict__ W2_g,
                const float* __restrict__ b2_g,
                float* __restrict__ out_g,
                float* __restrict__ attn_g) {
    extern __shared__ char smem[];
    const uint32_t sbase = smem_u32(smem);
    float* sC     = (float*)(smem + OFF_C);
    float* sQ     = (float*)(smem + OFF_Q);
    float* sW2    = (float*)(smem + OFF_W2);
    float* sB1b   = (float*)(smem + OFF_B1B);
    float* sScore = (float*)(smem + OFF_SCORE);
    float* sPart  = (float*)(smem + OFF_PART);
    float* sPOut  = (float*)(smem + OFF_POUT);

    const int b = blockIdx.x;
    const int t = threadIdx.x;
    const int lane = t & 31, w = t >> 5;
    const int len = klen_g[b];
    const float b2v = b2_g[0];

    // ---- weight tiles -> smem (straight uint4 copies, L2-hot) ----
    {
        const uint4* s1 = (const uint4*)&g_B1[0][0];
        uint4* d1 = (uint4*)(smem + OFF_B1H);
        #pragma unroll 4
        for (int i = t; i < (2 * A_BYTES) / 16; i += 256) d1[i] = s1[i];
        const uint4* s2 = (const uint4*)&g_B2[0][0];
        uint4* d2 = (uint4*)(smem + OFF_B2H);
        #pragma unroll 4
        for (int i = t; i < (2 * B2_BYTES) / 16; i += 256) d2[i] = s2[i];
    }
    if (t < 64) { sQ[t] = q_g[b * NE + t]; sW2[t] = W2_g[t]; sB1b[t] = b1_g[t]; }
    __syncthreads();   // sQ ready for Kp build

    // ---- c[h] = b0[h] + sum_e q[e] * Wq[e][h] ----
    if (t < NH1) {
        float acc = b0_g[t];
        #pragma unroll 8
        for (int e = 0; e < NE; e++) acc = fmaf(sQ[e], g_Wq[e * NH1 + t], acc);
        sC[t] = acc;
    }

    // ---- A1 = [keys | keys*q] bf16 hi/lo into padded smem ----
    for (int i = t; i < NS * 32; i += 256) {
        int s = i >> 5, p = i & 31;           // element pair (2p, 2p+1)
        float2 kv = *(const float2*)&keys_g[((size_t)b * NS + s) * NE + 2 * p];
        uint32_t hi, lo;
        split_pair(kv.x, kv.y, hi, lo);
        *(uint32_t*)(smem + OFF_AH + s * ASTRIDE + p * 4) = hi;
        *(uint32_t*)(smem + OFF_AL + s * ASTRIDE + p * 4) = lo;
        float q0 = sQ[2 * p], q1 = sQ[2 * p + 1];
        split_pair(kv.x * q0, kv.y * q1, hi, lo);
        *(uint32_t*)(smem + OFF_AH + s * ASTRIDE + 128 + p * 4) = hi;
        *(uint32_t*)(smem + OFF_AL + s * ASTRIDE + 128 + p * 4) = lo;
    }
    // zero pad rows 100..127 (both hi and lo)
    for (int i = t; i < 28 * 17 * 2; i += 256) {
        int m = i / (28 * 17), r = (i % (28 * 17)) / 17, cc = i % 17;
        *(uint4*)(smem + (m ? OFF_AL : OFF_AH) + (100 + r) * ASTRIDE + cc * 16) =
            make_uint4(0, 0, 0, 0);
    }
    __syncthreads();

    // ---- lane geometry for ldmatrix ----
    const uint32_t aRow = lane & 15;
    const uint32_t aCol = ((lane >> 4) & 1) * 16;           // bytes
    const uint32_t bRow = (lane & 7) + ((lane >> 4) & 1) * 8;
    const uint32_t bCol = ((lane >> 3) & 1) * 16;           // bytes

    const int mg = w >> 1, s0 = mg * 32;
    const uint32_t aBaseH0 = sbase + OFF_AH + (s0 + aRow) * ASTRIDE + aCol;
    const uint32_t aBaseH1 = aBaseH0 + 16 * ASTRIDE;
    const uint32_t aBaseL0 = aBaseH0 + A_BYTES;
    const uint32_t aBaseL1 = aBaseH1 + A_BYTES;

    // ================= GEMM1: D1[128s x 128h] = Kp @ Wcat =================
    float acc[16][4];
    {
        const int ng = w & 1, h0 = ng * 64;
        #pragma unroll
        for (int i = 0; i < 16; i++)
            #pragma unroll
            for (int j = 0; j < 4; j++) acc[i][j] = 0.f;

        uint32_t bBaseH[4], bBaseL[4];
        #pragma unroll
        for (int np = 0; np < 4; np++) {
            bBaseH[np] = sbase + OFF_B1H + (h0 + np * 16 + bRow) * ASTRIDE + bCol;
            bBaseL[np] = bBaseH[np] + A_BYTES;
        }

        #pragma unroll
        for (int k = 0; k < 8; k++) {
            const uint32_t ko = k * 32;
            uint32_t ah0[4], ah1[4], al0[4], al1[4];
            ldsm4(ah0, aBaseH0 + ko);
            ldsm4(ah1, aBaseH1 + ko);
            ldsm4(al0, aBaseL0 + ko);
            ldsm4(al1, aBaseL1 + ko);
            uint32_t bh[4][4], bl[4][4];
            #pragma unroll
            for (int np = 0; np < 4; np++) {
                ldsm4(bh[np], bBaseH[np] + ko);
                ldsm4(bl[np], bBaseL[np] + ko);
            }
            #pragma unroll
            for (int np = 0; np < 4; np++) {
                #pragma unroll
                for (int half = 0; half < 2; half++) {
                    const int nt = np * 2 + half;
                    const uint32_t bh0 = bh[np][half * 2], bh1 = bh[np][half * 2 + 1];
                    const uint32_t bl0 = bl[np][half * 2], bl1 = bl[np][half * 2 + 1];
                    mma_bf16(acc[nt],     ah0, bh0, bh1);
                    mma_bf16(acc[nt],     ah0, bl0, bl1);
                    mma_bf16(acc[nt],     al0, bh0, bh1);
                    mma_bf16(acc[8 + nt], ah1, bh0, bh1);
                    mma_bf16(acc[8 + nt], ah1, bl0, bl1);
                    mma_bf16(acc[8 + nt], al1, bh0, bh1);
                }
            }
        }
    }
    __syncthreads();   // done reading A1

    // ---- epilogue1: H0 = relu(D1 + c) -> split bf16 -> A region ----
    {
        const int ng = w & 1, h0 = ng * 64;
        #pragma unroll
        for (int mt = 0; mt < 2; mt++) {
            #pragma unroll
            for (int nt = 0; nt < 8; nt++) {
                const float* c = acc[mt * 8 + nt];
                const int row = s0 + mt * 16 + (lane >> 2);
                const int col = h0 + nt * 8 + (lane & 3) * 2;
                const float c0 = sC[col], c1 = sC[col + 1];
                uint32_t hi, lo;
                split_pair(fmaxf(c[0] + c0, 0.f), fmaxf(c[1] + c1, 0.f), hi, lo);
                *(uint32_t*)(smem + OFF_AH + row * ASTRIDE + col * 2) = hi;
                *(uint32_t*)(smem + OFF_AL + row * ASTRIDE + col * 2) = lo;
                split_pair(fmaxf(c[2] + c0, 0.f), fmaxf(c[3] + c1, 0.f), hi, lo);
                *(uint32_t*)(smem + OFF_AH + (row + 8) * ASTRIDE + col * 2) = hi;
                *(uint32_t*)(smem + OFF_AL + (row + 8) * ASTRIDE + col * 2) = lo;
            }
        }
    }
    __syncthreads();

    // ================= GEMM2: D2[128s x 64j] = H0 @ W1 =================
    float acc2[8][4];
    const int ng2 = w & 1, j0 = ng2 * 32;
    {
        #pragma unroll
        for (int i = 0; i < 8; i++)
            #pragma unroll
            for (int j = 0; j < 4; j++) acc2[i][j] = 0.f;

        uint32_t bBaseH[2], bBaseL[2];
        #pragma unroll
        for (int np = 0; np < 2; np++) {
            bBaseH[np] = sbase + OFF_B2H + (j0 + np * 16 + bRow) * ASTRIDE + bCol;
            bBaseL[np] = bBaseH[np] + B2_BYTES;
        }

        #pragma unroll
        for (int k = 0; k < 8; k++) {
            const uint32_t ko = k * 32;
            uint32_t ah0[4], ah1[4], al0[4], al1[4];
            ldsm4(ah0, aBaseH0 + ko);
            ldsm4(ah1, aBaseH1 + ko);
            ldsm4(al0, aBaseL0 + ko);
            ldsm4(al1, aBaseL1 + ko);
            uint32_t bh[2][4], bl[2][4];
            #pragma unroll
            for (int np = 0; np < 2; np++) {
                ldsm4(bh[np], bBaseH[np] + ko);
                ldsm4(bl[np], bBaseL[np] + ko);
            }
            #pragma unroll
            for (int np = 0; np < 2; np++) {
                #pragma unroll
                for (int half = 0; half < 2; half++) {
                    const int nt = np * 2 + half;
                    const uint32_t bh0 = bh[np][half * 2], bh1 = bh[np][half * 2 + 1];
                    const uint32_t bl0 = bl[np][half * 2], bl1 = bl[np][half * 2 + 1];
                    mma_bf16(acc2[nt],     ah0, bh0, bh1);
                    mma_bf16(acc2[nt],     ah0, bl0, bl1);
                    mma_bf16(acc2[nt],     al0, bh0, bh1);
                    mma_bf16(acc2[4 + nt], ah1, bh0, bh1);
                    mma_bf16(acc2[4 + nt], ah1, bl0, bl1);
                    mma_bf16(acc2[4 + nt], al1, bh0, bh1);
                }
            }
        }
    }

    // ---- epilogue2: scores = sum_j relu(D2 + b1)*W2 ----
    {
        float part[4] = {0.f, 0.f, 0.f, 0.f};   // [mt][rowhalf]
        #pragma unroll
        for (int mt = 0; mt < 2; mt++) {
            #pragma unroll
            for (int nt = 0; nt < 4; nt++) {
                const float* c = acc2[mt * 4 + nt];
                const int col = j0 + nt * 8 + (lane & 3) * 2;
                const float bb0 = sB1b[col], bb1 = sB1b[col + 1];
                const float w0v = sW2[col],  w1v = sW2[col + 1];
                part[mt * 2]     += fmaxf(c[0] + bb0, 0.f) * w0v + fmaxf(c[1] + bb1, 0.f) * w1v;
                part[mt * 2 + 1] += fmaxf(c[2] + bb0, 0.f) * w0v + fmaxf(c[3] + bb1, 0.f) * w1v;
            }
        }
        #pragma unroll
        for (int i = 0; i < 4; i++) {
            float v = part[i];
            v += __shfl_xor_sync(0xffffffffu, v, 1);
            v += __shfl_xor_sync(0xffffffffu, v, 2);
            if ((lane & 3) == 0) {
                const int row = s0 + (i >> 1) * 16 + (lane >> 2) + (i & 1) * 8;
                sPart[row * 2 + ng2] = v;
            }
        }
    }
    __syncthreads();
    if (t < 128) sScore[t] = sPart[t * 2] + sPart[t * 2 + 1] + b2v;
    __syncthreads();

    // ---- masked softmax (warp 0) ----
    if (t < 32) {
        float m = -1e30f;
        for (int s = t; s < NS; s += 32) {
            float v = (s < len) ? sScore[s] : -1e30f;
            m = fmaxf(m, v);
        }
        #pragma unroll
        for (int off = 16; off; off >>= 1) m = fmaxf(m, __shfl_xor_sync(0xffffffffu, m, off));
        float sum = 0.f;
        for (int s = t; s < NS; s += 32) {
            float v = (s < len) ? expf(sScore[s] - m) : 0.f;
            sScore[s] = v;
            sum += v;
        }
        #pragma unroll
        for (int off = 16; off; off >>= 1) sum += __shfl_xor_sync(0xffffffffu, sum, off);
        float inv = 1.f / sum;
        for (int s = t; s < NS; s += 32) sScore[s] *= inv;
    }
    __syncthreads();

    // ---- out[e] = sum_s attn[s] * keys[s][e] (keys L2-hot) ----
    {
        const int e = t & 63, g = t >> 6;
        const float* kb = keys_g + (size_t)b * NS * NE;
        float a = 0.f;
        for (int s = g; s < NS; s += 4) a = fmaf(sScore[s], kb[s * NE + e], a);
        sPOut[g * 64 + e] = a;
    }
    __syncthreads();
    if (t < 64)
        out_g[(size_t)b * NE + t] = sPOut[t] + sPOut[64 + t] + sPOut[128 + t] + sPOut[192 + t];
    if (attn_g && t < NS) attn_g[(size_t)b * NS + t] = sScore[t];
}

extern "C" void kernel_launch(void* const* d_in, const int* in_sizes, int n_in,
                              void* d_out, int out_size) {
    const float* query = (const float*)d_in[0];
    const float* keys  = (const float*)d_in[1];
    const int*   klen  = (const int*)  d_in[2];
    const float* W0    = (const float*)d_in[3];
    const float* b0    = (const float*)d_in[4];
    const float* W1    = (const float*)d_in[5];
    const float* b1    = (const float*)d_in[6];
    const float* W2    = (const float*)d_in[7];
    const float* b2    = (const float*)d_in[8];

    float* outp  = (float*)d_out;
    float* attnp = (out_size >= NB * NE + NB * NS) ? outp + (size_t)NB * NE : nullptr;

    cudaFuncSetAttribute(din_kernel, cudaFuncAttributeMaxDynamicSharedMemorySize, SMEM_TOTAL);

    prep_kernel<<<64, 512>>>(W0, W1);
    din_kernel<<<NB, 256, SMEM_TOTAL>>>(query, keys, klen, b0, b1, W2, b2, outp, attnp);
}